// round 15
// baseline (speedup 1.0000x reference)
#include <cuda_runtime.h>
#include <cuda_fp16.h>
#include <math.h>
#include <stdint.h>

#define BB 4
#define TT 256
#define UU 64
#define DD 640
#define HH 640
#define VV 1024
#define MTOT (BB*TT*UU)   // 65536
#define L2E 1.4426950408889634f

#define AROW 648          // f16 units per A row in SMEM
#define BROW 24           // f16 units per B row in SMEM (16 + 8 pad)
#define BROWB 48
#define BBUF (256*BROWB)  // bytes per B stage = 12288 (BK=16)
#define NSTEP 160         // 4 chunks x 40 k-steps
#define NTHR 256          // 8 warps: wm 0..1 x wn 0..3, warp tile 32x64; M=64

// ---- static device scratch ----
__device__ float  g_enc[BB*TT*HH];
__device__ float  g_pred[BB*UU*HH];
__device__ float  g_part[5*BB*TT*HH];
__device__ float  g_partp[5*BB*UU*HH];
__device__ __half g_w16t[VV*HH];                 // W_fc^T f16: [n][k]
__device__ __half g_logits[(size_t)MTOT*VV];     // staged logits f16 (chunks 0-2)

__device__ __forceinline__ uint32_t smem_u32(const void* p) {
    uint32_t a;
    asm("{ .reg .u64 t; cvta.to.shared.u64 t, %1; cvt.u32.u64 %0, t; }"
        : "=r"(a) : "l"(p));
    return a;
}
__device__ __forceinline__ void cpasync16cg(uint32_t dst, const void* src) {
    asm volatile("cp.async.cg.shared.global [%0], [%1], 16;" ::"r"(dst), "l"(src));
}
#define CP_COMMIT() asm volatile("cp.async.commit_group;")
#define CP_WAIT(n) asm volatile("cp.async.wait_group %0;" ::"n"(n))

__device__ __forceinline__ void ldsm_x4(uint32_t* r, uint32_t addr) {
    asm volatile("ldmatrix.sync.aligned.m8n8.x4.shared.b16 {%0,%1,%2,%3}, [%4];"
                 : "=r"(r[0]), "=r"(r[1]), "=r"(r[2]), "=r"(r[3]) : "r"(addr));
}
__device__ __forceinline__ float ex2sum2(float x0, float x1) {
    __half2 h = __floats2half2_rn(x0, x1);
    unsigned int u = *(unsigned int*)&h, o;
    asm("ex2.approx.f16x2 %0, %1;" : "=r"(o) : "r"(u));
    float2 f = __half22float2(*(__half2*)&o);
    return f.x + f.y;
}
__device__ __forceinline__ uint32_t tanh2(float x0, float x1) {
    __half2 h = __floats2half2_rn(x0, x1);
    unsigned int u = *(unsigned int*)&h, o;
    asm("tanh.approx.f16x2 %0, %1;" : "=r"(o) : "r"(u));
    return o;
}

// ===========================================================================
// Projection GEMM (split-K by 5)
// ===========================================================================
__global__ __launch_bounds__(256) void proj_gemm(const float* __restrict__ X,
                                                 const float* __restrict__ W, int which) {
    float* C = which ? g_partp : g_part;
    const int Mrows = which ? (BB * UU) : (BB * TT);
    __shared__ float As[16][65];
    __shared__ float Bs[16][65];
    const int tid = threadIdx.x;
    const int bm = blockIdx.x * 64, bn = blockIdx.y * 64, kz = blockIdx.z;
    const int ty = tid / 16, tx = tid % 16;
    float c[4][4];
#pragma unroll
    for (int i = 0; i < 4; i++)
#pragma unroll
        for (int j = 0; j < 4; j++) c[i][j] = 0.f;
    for (int k0 = kz * 128; k0 < kz * 128 + 128; k0 += 16) {
        for (int l = tid; l < 64 * 16; l += 256) {
            int row = l >> 4, kk = l & 15;
            As[kk][row] = X[(size_t)(bm + row) * DD + k0 + kk];
        }
        for (int l = tid; l < 16 * 64; l += 256) {
            int kk = l >> 6, col = l & 63;
            Bs[kk][col] = W[(size_t)(k0 + kk) * HH + bn + col];
        }
        __syncthreads();
#pragma unroll
        for (int kk = 0; kk < 16; kk++) {
            float a[4], b[4];
#pragma unroll
            for (int i = 0; i < 4; i++) a[i] = As[kk][ty * 4 + i];
#pragma unroll
            for (int j = 0; j < 4; j++) b[j] = Bs[kk][tx * 4 + j];
#pragma unroll
            for (int i = 0; i < 4; i++)
#pragma unroll
                for (int j = 0; j < 4; j++) c[i][j] += a[i] * b[j];
        }
        __syncthreads();
    }
    float* Cz = C + (size_t)kz * Mrows * HH;
#pragma unroll
    for (int i = 0; i < 4; i++)
#pragma unroll
        for (int j = 0; j < 4; j++)
            Cz[(size_t)(bm + ty * 4 + i) * HH + bn + tx * 4 + j] = c[i][j];
}

// ===========================================================================
// Fused: proj reduce (blocks 0..3199) + W_fc fp32->f16 transpose (3200..3839)
// ===========================================================================
__global__ __launch_bounds__(256) void reduce_convert(const float* __restrict__ b_enc,
                                                      const float* __restrict__ b_pred,
                                                      const float* __restrict__ Wfc) {
    __shared__ float t[32][33];
    const int encN = BB * TT * HH, predN = BB * UU * HH;
    if (blockIdx.x < 3200) {
        int idx = blockIdx.x * 256 + threadIdx.x;
        if (idx < encN) {
            float s = b_enc[idx % HH];
#pragma unroll
            for (int z = 0; z < 5; z++) s += g_part[(size_t)z * encN + idx];
            g_enc[idx] = s;
        } else {
            int j = idx - encN;
            if (j < predN) {
                float s = b_pred[j % HH];
#pragma unroll
                for (int z = 0; z < 5; z++) s += g_partp[(size_t)z * predN + j];
                g_pred[j] = s;
            }
        }
    } else {
        int bid = blockIdx.x - 3200;           // 0..639
        int n0 = (bid & 31) * 32, k0 = (bid >> 5) * 32;
        int tx = threadIdx.x & 31, ty = threadIdx.x >> 5;
#pragma unroll
        for (int j = 0; j < 4; j++)
            t[ty + 8 * j][tx] = Wfc[(size_t)(k0 + ty + 8 * j) * VV + n0 + tx];
        __syncthreads();
#pragma unroll
        for (int j = 0; j < 4; j++)
            g_w16t[(size_t)(n0 + ty + 8 * j) * HH + k0 + tx] =
                __float2half(t[tx][ty + 8 * j]);
    }
}

// ===========================================================================
// Main kernel: M-tile 64, 256 threads (8 warps, warp tile 32x64),
// TWO CTAs PER SM (smem 109.3KB, launch_bounds(256,2)) — independent
// pipelines/barrier domains overlap each other's latency stalls.
// BK=16, 2 B buffers, one __syncthreads per k-step, prefetch after sync.
// Fused tanh prologue, online log-softmax, chunks 0-2 staged, ch3 direct.
// ===========================================================================
#define SM_A 0
#define SM_B (64 * AROW * 2)           // 82944
#define SM_RED (SM_B + 2 * BBUF)       // 107520
#define SM_SCM (SM_RED + 1024)         // 108544
#define SM_RMAX (SM_SCM + 256)         // 108800
#define SM_RSUM (SM_RMAX + 256)        // 109056
#define SM_TOTAL (SM_RSUM + 256)       // 109312

__global__ __launch_bounds__(NTHR, 2) void joint_gemm(const float* __restrict__ bfc,
                                                      float* __restrict__ out) {
    extern __shared__ char smc[];
    const uint32_t sbase = smem_u32(smc);
    float* red = (float*)(smc + SM_RED);    // [4][64] indexed by wn
    float* scm = (float*)(smc + SM_SCM);    // [64]
    float* rmax = (float*)(smc + SM_RMAX);  // [64]
    float* rsum = (float*)(smc + SM_RSUM);  // [64]

    const int tid = threadIdx.x;
    const int lane = tid & 31;
    const int warp = tid >> 5;
    const int wm = warp >> 2;   // 0..1 -> rows 32*wm
    const int wn = warp & 3;    // 0..3 -> cols 64*wn
    const int g = lane >> 2;    // 0..7
    const int t4 = lane & 3;    // 0..3
    const size_t row0 = (size_t)blockIdx.x * 64;

    // ---- per-thread B staging (incremental): row tid, 32B per stage ----
    const uint32_t bdst0 = sbase + SM_B + tid * BROWB;
    const __half* bsrc = g_w16t + (size_t)tid * HH;   // stage 0 src (k=0)

    // ---- prologue: stage 0 into buf 0 ----
    cpasync16cg(bdst0, bsrc);
    cpasync16cg(bdst0 + 16, bsrc + 8);
    CP_COMMIT();
    bsrc += 16;                 // next stage to load = 1
    int lks = 1;                // k-step-in-chunk of next load

    // ---- build A = f16(tanh(enc_row + pred_row)) directly in SMEM ----
    {
        const float* encr = g_enc + (row0 >> 6) * (size_t)HH;   // one enc row
        const float* predb = g_pred + (row0 / (TT * UU)) * (size_t)(UU * HH);
        for (int e = tid; e < 64 * 160; e += NTHR) {
            int i = e / 160;
            int h4 = (e - i * 160) * 4;
            float4 p = *(const float4*)&predb[(size_t)i * HH + h4];
            float4 q = *(const float4*)&encr[h4];
            uint2 o;
            o.x = tanh2(p.x + q.x, p.y + q.y);
            o.y = tanh2(p.z + q.z, p.w + q.w);
            *(uint2*)(smc + SM_A + i * (AROW * 2) + h4 * 2) = o;
        }
    }
    if (tid < 64) {
        rmax[tid] = -INFINITY;
        rsum[tid] = 0.f;
    }

    float d[2][8][4];
#pragma unroll
    for (int mt = 0; mt < 2; mt++)
#pragma unroll
        for (int nt = 0; nt < 8; nt++)
#pragma unroll
            for (int q = 0; q < 4; q++) d[mt][nt][q] = 0.f;

    const uint32_t a_lane_row = (uint32_t)(wm * 32 + (lane & 15));
    const uint32_t a_lane_coloff = (uint32_t)((lane >> 4) << 3);
    const uint32_t b_lane_n = (uint32_t)(wn * 64 + (lane & 7) + ((lane >> 4) << 3));
    const uint32_t b_lane_koff = (uint32_t)(((lane >> 3) & 1) << 3);

    const uint32_t abase0 =
        sbase + SM_A + (a_lane_row * AROW + a_lane_coloff) * 2;
    const uint32_t bfrag0 = sbase + SM_B + (b_lane_n * BROW + b_lane_koff) * 2;

    int gi = 0;
    for (int ch = 0; ch < 4; ch++) {
        uint32_t abase = abase0;   // k=0 of this chunk
        for (int ks = 0; ks < 40; ks++, gi++) {
            CP_WAIT(0);       // stage gi landed
            __syncthreads();  // publish gi; certify gi-1 consumed (its buf free)

            // prefetch stage gi+1 into buf (gi+1)&1 (overlaps compute of gi)
            if (gi + 1 < NSTEP) {
                uint32_t pd = bdst0 + (((uint32_t)gi + 1u) & 1u) * BBUF;
                cpasync16cg(pd, bsrc);
                cpasync16cg(pd + 16, bsrc + 8);
                CP_COMMIT();
                if (++lks == 40) {
                    lks = 0;
                    bsrc += 256 * HH - 39 * 16;   // next chunk, k=0
                } else {
                    bsrc += 16;
                }
            }

            const uint32_t bbase = bfrag0 + ((uint32_t)gi & 1u) * BBUF;

            uint32_t a[2][4];
#pragma unroll
            for (int mt = 0; mt < 2; mt++)
                ldsm_x4(a[mt], abase + mt * 16 * (AROW * 2));

#pragma unroll
            for (int p = 0; p < 4; p++) {
                uint32_t b[4];
                ldsm_x4(b, bbase + p * 16 * (BROW * 2));
#pragma unroll
                for (int mt = 0; mt < 2; mt++) {
                    asm volatile(
                        "mma.sync.aligned.m16n8k16.row.col.f32.f16.f16.f32 "
                        "{%0,%1,%2,%3}, {%4,%5,%6,%7}, {%8,%9}, {%0,%1,%2,%3};"
                        : "+f"(d[mt][2 * p][0]), "+f"(d[mt][2 * p][1]),
                          "+f"(d[mt][2 * p][2]), "+f"(d[mt][2 * p][3])
                        : "r"(a[mt][0]), "r"(a[mt][1]), "r"(a[mt][2]),
                          "r"(a[mt][3]), "r"(b[0]), "r"(b[1]));
                    asm volatile(
                        "mma.sync.aligned.m16n8k16.row.col.f32.f16.f16.f32 "
                        "{%0,%1,%2,%3}, {%4,%5,%6,%7}, {%8,%9}, {%0,%1,%2,%3};"
                        : "+f"(d[mt][2 * p + 1][0]), "+f"(d[mt][2 * p + 1][1]),
                          "+f"(d[mt][2 * p + 1][2]), "+f"(d[mt][2 * p + 1][3])
                        : "r"(a[mt][0]), "r"(a[mt][1]), "r"(a[mt][2]),
                          "r"(a[mt][3]), "r"(b[2]), "r"(b[3]));
                }
            }
            abase += 32;  // 16 k consumed (f16 = 2B)
        }

        // ================= per-chunk epilogue =================
        {
            // ---- bias (L2-hot gmem) ----
#pragma unroll
            for (int nt = 0; nt < 8; nt++) {
                int c = ch * 256 + wn * 64 + nt * 8 + t4 * 2;
                float b0 = __ldg(&bfc[c]), b1 = __ldg(&bfc[c + 1]);
#pragma unroll
                for (int mt = 0; mt < 2; mt++) {
                    d[mt][nt][0] += b0;
                    d[mt][nt][1] += b1;
                    d[mt][nt][2] += b0;
                    d[mt][nt][3] += b1;
                }
            }
            // ---- chunk row max ----
            float lm[2][2];
#pragma unroll
            for (int mt = 0; mt < 2; mt++) {
                float m0 = -INFINITY, m1 = -INFINITY;
#pragma unroll
                for (int nt = 0; nt < 8; nt++) {
                    m0 = fmaxf(m0, fmaxf(d[mt][nt][0], d[mt][nt][1]));
                    m1 = fmaxf(m1, fmaxf(d[mt][nt][2], d[mt][nt][3]));
                }
                lm[mt][0] = m0;
                lm[mt][1] = m1;
            }
#pragma unroll
            for (int mt = 0; mt < 2; mt++)
#pragma unroll
                for (int hh = 0; hh < 2; hh++) {
                    float v = lm[mt][hh];
                    v = fmaxf(v, __shfl_xor_sync(0xffffffffu, v, 1));
                    v = fmaxf(v, __shfl_xor_sync(0xffffffffu, v, 2));
                    lm[mt][hh] = v;
                }
            if (t4 == 0) {
#pragma unroll
                for (int mt = 0; mt < 2; mt++)
#pragma unroll
                    for (int hh = 0; hh < 2; hh++)
                        red[wn * 64 + wm * 32 + mt * 16 + hh * 8 + g] = lm[mt][hh];
            }
            __syncthreads();
            if (tid < 64)
                scm[tid] = fmaxf(fmaxf(red[tid], red[64 + tid]),
                                 fmaxf(red[128 + tid], red[192 + tid]));
            __syncthreads();

            // ---- chunk sum of exp ----
            float ls[2][2];
#pragma unroll
            for (int mt = 0; mt < 2; mt++)
#pragma unroll
                for (int hh = 0; hh < 2; hh++) {
                    float cm = scm[wm * 32 + mt * 16 + hh * 8 + g];
                    float s = 0.f;
#pragma unroll
                    for (int nt = 0; nt < 8; nt++)
                        s += ex2sum2((d[mt][nt][2 * hh] - cm) * L2E,
                                     (d[mt][nt][2 * hh + 1] - cm) * L2E);
                    ls[mt][hh] = s;
                }
#pragma unroll
            for (int mt = 0; mt < 2; mt++)
#pragma unroll
                for (int hh = 0; hh < 2; hh++) {
                    float v = ls[mt][hh];
                    v += __shfl_xor_sync(0xffffffffu, v, 1);
                    v += __shfl_xor_sync(0xffffffffu, v, 2);
                    ls[mt][hh] = v;
                }
            if (t4 == 0) {
#pragma unroll
                for (int mt = 0; mt < 2; mt++)
#pragma unroll
                    for (int hh = 0; hh < 2; hh++)
                        red[wn * 64 + wm * 32 + mt * 16 + hh * 8 + g] = ls[mt][hh];
            }
            __syncthreads();
            if (tid < 64) {
                float cs = red[tid] + red[64 + tid] + red[128 + tid] + red[192 + tid];
                float mo = rmax[tid];
                float mn = fmaxf(mo, scm[tid]);
                rsum[tid] = rsum[tid] * exp2f((mo - mn) * L2E) +
                            cs * exp2f((scm[tid] - mn) * L2E);
                rmax[tid] = mn;
            }

            if (ch < 3) {
                // ---- stage f16 logits (streaming stores) + reset accums ----
#pragma unroll
                for (int mt = 0; mt < 2; mt++)
#pragma unroll
                    for (int hh = 0; hh < 2; hh++) {
                        size_t r = row0 + wm * 32 + mt * 16 + hh * 8 + g;
#pragma unroll
                        for (int nt = 0; nt < 8; nt++) {
                            int c = ch * 256 + wn * 64 + nt * 8 + t4 * 2;
                            __half2 hv = __floats2half2_rn(d[mt][nt][2 * hh],
                                                           d[mt][nt][2 * hh + 1]);
                            __stcs((__half2*)&g_logits[r * VV + c], hv);
                        }
                    }
#pragma unroll
                for (int mt = 0; mt < 2; mt++)
#pragma unroll
                    for (int nt = 0; nt < 8; nt++)
#pragma unroll
                        for (int q = 0; q < 4; q++) d[mt][nt][q] = 0.f;
            }
            // ch==3: keep biased logits in registers for direct output below
        }
    }

    // ---- finalize: rls ----
    __syncthreads();
    if (tid < 64) scm[tid] = logf(rsum[tid]) + rmax[tid];
    __syncthreads();

    // ---- chunk 3 output directly from registers ----
#pragma unroll
    for (int mt = 0; mt < 2; mt++)
#pragma unroll
        for (int hh = 0; hh < 2; hh++) {
            int rl = wm * 32 + mt * 16 + hh * 8 + g;
            float rls = scm[rl];
            size_t r = row0 + rl;
#pragma unroll
            for (int nt = 0; nt < 8; nt++) {
                int c = 768 + wn * 64 + nt * 8 + t4 * 2;
                float2 o;
                o.x = d[mt][nt][2 * hh] - rls;
                o.y = d[mt][nt][2 * hh + 1] - rls;
                __stcs((float2*)&out[r * VV + c], o);
            }
        }

    // ---- normalize staged chunks 0-2 (cols 0..767) ----
    for (int p = tid; p < 64 * 192; p += NTHR) {
        int r = p / 192;
        int c4 = p - r * 192;
        float rls = scm[r];
        uint2 lv = __ldcs((const uint2*)&g_logits[(row0 + r) * VV + c4 * 4]);
        float2 f0 = __half22float2(*(__half2*)&lv.x);
        float2 f1 = __half22float2(*(__half2*)&lv.y);
        float4 o;
        o.x = f0.x - rls;
        o.y = f0.y - rls;
        o.z = f1.x - rls;
        o.w = f1.y - rls;
        __stcs((float4*)&out[(row0 + r) * VV + c4 * 4], o);
    }
}

// ===========================================================================
extern "C" void kernel_launch(void* const* d_in, const int* in_sizes, int n_in,
                              void* d_out, int out_size) {
    const float* enc_out = (const float*)d_in[0];
    const float* pred_out = (const float*)d_in[1];
    const float* W_enc = (const float*)d_in[2];
    const float* b_enc = (const float*)d_in[3];
    const float* W_pred = (const float*)d_in[4];
    const float* b_pred = (const float*)d_in[5];
    const float* W_fc = (const float*)d_in[6];
    const float* b_fc = (const float*)d_in[7];
    float* out = (float*)d_out;

    cudaFuncSetAttribute(joint_gemm, cudaFuncAttributeMaxDynamicSharedMemorySize,
                         SM_TOTAL);

    proj_gemm<<<dim3((BB * TT) / 64, HH / 64, 5), 256>>>(enc_out, W_enc, 0);
    proj_gemm<<<dim3((BB * UU) / 64, HH / 64, 5), 256>>>(pred_out, W_pred, 1);
    reduce_convert<<<3200 + 640, 256>>>(b_enc, b_pred, W_fc);
    joint_gemm<<<MTOT / 64, NTHR, SM_TOTAL>>>(b_fc, out);
}

// round 16
// speedup vs baseline: 1.0408x; 1.0408x over previous
#include <cuda_runtime.h>
#include <cuda_fp16.h>
#include <math.h>
#include <stdint.h>

#define BB 4
#define TT 256
#define UU 64
#define DD 640
#define HH 640
#define VV 1024
#define MTOT (BB*TT*UU)   // 65536
#define L2E 1.4426950408889634f

#define AROW 648          // f16 units per A row in SMEM
#define BROW 40           // f16 units per B row in SMEM (32 + 8 pad)
#define BROWB 80
#define BBUF (256*BROWB)  // bytes per B stage = 20480 (BK=32)
#define NSTAGE 80         // 4 chunks x 20 stages (32 k each)
#define NTHR 512          // 16 warps: wm 0..3 x wn 0..3, warp tile 32x64

// ---- static device scratch ----
__device__ float  g_enc[BB*TT*HH];
__device__ float  g_pred[BB*UU*HH];
__device__ __half g_w16t[VV*HH];                 // W_fc^T f16: [n][k]
__device__ __half g_logits[(size_t)MTOT*VV];     // staged logits f16 (chunks 0-2)

__device__ __forceinline__ uint32_t smem_u32(const void* p) {
    uint32_t a;
    asm("{ .reg .u64 t; cvta.to.shared.u64 t, %1; cvt.u32.u64 %0, t; }"
        : "=r"(a) : "l"(p));
    return a;
}
__device__ __forceinline__ void cpasync16cg(uint32_t dst, const void* src) {
    asm volatile("cp.async.cg.shared.global [%0], [%1], 16;" ::"r"(dst), "l"(src));
}
#define CP_COMMIT() asm volatile("cp.async.commit_group;")
#define CP_WAIT(n) asm volatile("cp.async.wait_group %0;" ::"n"(n))

__device__ __forceinline__ void ldsm_x4(uint32_t* r, uint32_t addr) {
    asm volatile("ldmatrix.sync.aligned.m8n8.x4.shared.b16 {%0,%1,%2,%3}, [%4];"
                 : "=r"(r[0]), "=r"(r[1]), "=r"(r[2]), "=r"(r[3]) : "r"(addr));
}
__device__ __forceinline__ float ex2sum2(float x0, float x1) {
    __half2 h = __floats2half2_rn(x0, x1);
    unsigned int u = *(unsigned int*)&h, o;
    asm("ex2.approx.f16x2 %0, %1;" : "=r"(o) : "r"(u));
    float2 f = __half22float2(*(__half2*)&o);
    return f.x + f.y;
}
__device__ __forceinline__ uint32_t tanh2(float x0, float x1) {
    __half2 h = __floats2half2_rn(x0, x1);
    unsigned int u = *(unsigned int*)&h, o;
    asm("tanh.approx.f16x2 %0, %1;" : "=r"(o) : "r"(u));
    return o;
}

// ===========================================================================
// ONE pre-kernel, 3 segments by blockIdx.x:
//   [0, 320)    : enc proj  (1024x640 @ 640x640 + bias), tile 32x64, K=640
//   [320, 400)  : pred proj (256x640  @ 640x640 + bias), tile 32x64
//   [400, 1040) : W_fc fp32 [k][n] -> f16 transposed [n][k]
// ===========================================================================
__global__ __launch_bounds__(256) void pre_kernel(const float* __restrict__ enc_out,
                                                  const float* __restrict__ pred_out,
                                                  const float* __restrict__ W_enc,
                                                  const float* __restrict__ b_enc,
                                                  const float* __restrict__ W_pred,
                                                  const float* __restrict__ b_pred,
                                                  const float* __restrict__ Wfc) {
    __shared__ float As[16][33];   // [kk][row] 32 rows
    __shared__ float Bs[16][65];   // [kk][col] 64 cols
    const int tid = threadIdx.x;
    const int bid = blockIdx.x;

    if (bid >= 400) {
        // ---- W_fc convert (shared mem reuse via Bs+As as a 32x33 tile) ----
        __shared__ float t[32][33];
        int i = bid - 400;                 // 0..639
        int n0 = (i & 31) * 32;            // 32 n-blocks
        int k0 = (i >> 5) * 32;            // 20 k-blocks
        int tx = tid & 31, ty = tid >> 5;  // ty 0..7
#pragma unroll
        for (int j = 0; j < 4; j++)
            t[ty + 8 * j][tx] = Wfc[(size_t)(k0 + ty + 8 * j) * VV + n0 + tx];
        __syncthreads();
#pragma unroll
        for (int j = 0; j < 4; j++)
            g_w16t[(size_t)(n0 + ty + 8 * j) * HH + k0 + tx] =
                __float2half(t[tx][ty + 8 * j]);
        return;
    }

    // ---- projection segment ----
    const float* X;
    const float* W;
    const float* bias;
    float* C;
    int bm, bn;
    if (bid < 320) {
        X = enc_out; W = W_enc; bias = b_enc; C = g_enc;
        bm = (bid / 10) * 32;
        bn = (bid % 10) * 64;
    } else {
        int i = bid - 320;
        X = pred_out; W = W_pred; bias = b_pred; C = g_pred;
        bm = (i / 10) * 32;
        bn = (i % 10) * 64;
    }

    const int ty = tid >> 4;   // 0..15 -> rows ty*2, ty*2+1
    const int tx = tid & 15;   // 0..15 -> cols tx*4..+3
    float c[2][4];
#pragma unroll
    for (int i = 0; i < 2; i++)
#pragma unroll
        for (int j = 0; j < 4; j++) c[i][j] = 0.f;

    for (int k0 = 0; k0 < DD; k0 += 16) {
        // A: 32 rows x 16 k = 512 elems
        for (int l = tid; l < 512; l += 256) {
            int row = l >> 4, kk = l & 15;
            As[kk][row] = X[(size_t)(bm + row) * DD + k0 + kk];
        }
        // B: 16 k x 64 cols = 1024 elems
        for (int l = tid; l < 1024; l += 256) {
            int kk = l >> 6, col = l & 63;
            Bs[kk][col] = W[(size_t)(k0 + kk) * HH + bn + col];
        }
        __syncthreads();
#pragma unroll
        for (int kk = 0; kk < 16; kk++) {
            float a0 = As[kk][ty * 2], a1 = As[kk][ty * 2 + 1];
            float b0 = Bs[kk][tx * 4 + 0], b1 = Bs[kk][tx * 4 + 1];
            float b2 = Bs[kk][tx * 4 + 2], b3 = Bs[kk][tx * 4 + 3];
            c[0][0] += a0 * b0; c[0][1] += a0 * b1;
            c[0][2] += a0 * b2; c[0][3] += a0 * b3;
            c[1][0] += a1 * b0; c[1][1] += a1 * b1;
            c[1][2] += a1 * b2; c[1][3] += a1 * b3;
        }
        __syncthreads();
    }
#pragma unroll
    for (int i = 0; i < 2; i++)
#pragma unroll
        for (int j = 0; j < 4; j++)
            C[(size_t)(bm + ty * 2 + i) * HH + bn + tx * 4 + j] =
                c[i][j] + bias[bn + tx * 4 + j];
}

// ===========================================================================
// Main kernel (R13, at the fallback-HMMA throughput wall): M-tile 128,
// 512 threads, warp tile 32x64, BK=32 stages / 3 buffers, fused tanh
// prologue, online log-softmax, chunks 0-2 staged f16, chunk 3 direct.
// ===========================================================================
#define SM_A 0
#define SM_B (128 * AROW * 2)          // 165888
#define SM_RED (SM_B + 3 * BBUF)       // 227328
#define SM_SCM (SM_RED + 2048)         // 229376
#define SM_RMAX (SM_SCM + 512)         // 229888
#define SM_RSUM (SM_RMAX + 512)        // 230400
#define SM_TOTAL (SM_RSUM + 512)       // 230912

__global__ __launch_bounds__(NTHR, 1) void joint_gemm(const float* __restrict__ bfc,
                                                      float* __restrict__ out) {
    extern __shared__ char smc[];
    const uint32_t sbase = smem_u32(smc);
    float* red = (float*)(smc + SM_RED);    // [4][128] indexed by wn
    float* scm = (float*)(smc + SM_SCM);
    float* rmax = (float*)(smc + SM_RMAX);
    float* rsum = (float*)(smc + SM_RSUM);

    const int tid = threadIdx.x;
    const int lane = tid & 31;
    const int warp = tid >> 5;
    const int wm = warp >> 2;   // 0..3 -> rows 32*wm
    const int wn = warp & 3;    // 0..3 -> cols 64*wn
    const int g = lane >> 2;    // 0..7
    const int t4 = lane & 3;    // 0..3
    const size_t row0 = (size_t)blockIdx.x * 128;

    const int bn_row = tid >> 1;          // 0..255
    const int bh = tid & 1;               // 0..1
    const uint32_t bdst0 = sbase + SM_B + bn_row * BROWB + bh * 32;
    const __half* bsrc = g_w16t + (size_t)bn_row * HH + bh * 16;  // stage 0 src

    // ---- prologue: stages 0,1 ----
    cpasync16cg(bdst0 + 0 * BBUF, bsrc);
    cpasync16cg(bdst0 + 0 * BBUF + 16, bsrc + 8);
    CP_COMMIT();
    cpasync16cg(bdst0 + 1 * BBUF, bsrc + 32);
    cpasync16cg(bdst0 + 1 * BBUF + 16, bsrc + 40);
    CP_COMMIT();
    bsrc += 64;
    int lks = 2;
    int pbuf = 2;

    // ---- build A = f16(tanh(enc_row + pred_row)) directly in SMEM ----
    {
        const float* predb = g_pred + (row0 / (TT * UU)) * (size_t)(UU * HH);
        for (int e = tid; e < 128 * 160; e += NTHR) {
            int i = e / 160;
            int h4 = (e - i * 160) * 4;
            const float* encr = g_enc + (size_t)((row0 + i) >> 6) * HH;
            const float* predr = predb + (size_t)((row0 + i) & 63) * HH;
            float4 p = *(const float4*)&predr[h4];
            float4 q = *(const float4*)&encr[h4];
            uint2 o;
            o.x = tanh2(p.x + q.x, p.y + q.y);
            o.y = tanh2(p.z + q.z, p.w + q.w);
            *(uint2*)(smc + SM_A + i * (AROW * 2) + h4 * 2) = o;
        }
    }
    if (tid < 128) {
        rmax[tid] = -INFINITY;
        rsum[tid] = 0.f;
    }

    float d[2][8][4];
#pragma unroll
    for (int mt = 0; mt < 2; mt++)
#pragma unroll
        for (int nt = 0; nt < 8; nt++)
#pragma unroll
            for (int q = 0; q < 4; q++) d[mt][nt][q] = 0.f;

    const uint32_t a_lane_row = (uint32_t)(wm * 32 + (lane & 15));
    const uint32_t a_lane_coloff = (uint32_t)((lane >> 4) << 3);
    const uint32_t b_lane_n = (uint32_t)(wn * 64 + (lane & 7) + ((lane >> 4) << 3));
    const uint32_t b_lane_koff = (uint32_t)(((lane >> 3) & 1) << 3);

    const uint32_t abase0 =
        sbase + SM_A + (a_lane_row * AROW + a_lane_coloff) * 2;
    const uint32_t bfrag0 = sbase + SM_B + (b_lane_n * BROW + b_lane_koff) * 2;

    int gs = 0;
    int cbuf = 0;
    for (int ch = 0; ch < 4; ch++) {
        uint32_t abase = abase0;
        for (int it = 0; it < 20; it++, gs++) {
            __syncthreads();  // all warps done reading buffer pbuf (prev use)

            if (gs + 2 < NSTAGE) {
                cpasync16cg(bdst0 + pbuf * BBUF, bsrc);
                cpasync16cg(bdst0 + pbuf * BBUF + 16, bsrc + 8);
                CP_COMMIT();
                CP_WAIT(2);   // retire group of stage gs
                if (++lks == 20) {
                    lks = 0;
                    bsrc += 256 * HH - 19 * 32;
                } else {
                    bsrc += 32;
                }
                if (++pbuf == 3) pbuf = 0;
            } else {
                CP_WAIT(0);
            }
            __syncthreads();  // stage gs visible to all warps

            const uint32_t bstage = bfrag0 + (uint32_t)cbuf * BBUF;
            if (++cbuf == 3) cbuf = 0;

#pragma unroll
            for (int s = 0; s < 2; s++) {
                uint32_t a[2][4];
#pragma unroll
                for (int mt = 0; mt < 2; mt++)
                    ldsm_x4(a[mt], abase + s * 32 + mt * 16 * (AROW * 2));
                const uint32_t bb = bstage + s * 32;
#pragma unroll
                for (int p = 0; p < 4; p++) {
                    uint32_t b[4];
                    ldsm_x4(b, bb + p * 16 * (BROW * 2));
#pragma unroll
                    for (int mt = 0; mt < 2; mt++) {
                        asm volatile(
                            "mma.sync.aligned.m16n8k16.row.col.f32.f16.f16.f32 "
                            "{%0,%1,%2,%3}, {%4,%5,%6,%7}, {%8,%9}, {%0,%1,%2,%3};"
                            : "+f"(d[mt][2 * p][0]), "+f"(d[mt][2 * p][1]),
                              "+f"(d[mt][2 * p][2]), "+f"(d[mt][2 * p][3])
                            : "r"(a[mt][0]), "r"(a[mt][1]), "r"(a[mt][2]),
                              "r"(a[mt][3]), "r"(b[0]), "r"(b[1]));
                        asm volatile(
                            "mma.sync.aligned.m16n8k16.row.col.f32.f16.f16.f32 "
                            "{%0,%1,%2,%3}, {%4,%5,%6,%7}, {%8,%9}, {%0,%1,%2,%3};"
                            : "+f"(d[mt][2 * p + 1][0]), "+f"(d[mt][2 * p + 1][1]),
                              "+f"(d[mt][2 * p + 1][2]), "+f"(d[mt][2 * p + 1][3])
                            : "r"(a[mt][0]), "r"(a[mt][1]), "r"(a[mt][2]),
                              "r"(a[mt][3]), "r"(b[2]), "r"(b[3]));
                    }
                }
            }
            abase += 64;
        }

        // ================= per-chunk epilogue =================
        {
#pragma unroll
            for (int nt = 0; nt < 8; nt++) {
                int c = ch * 256 + wn * 64 + nt * 8 + t4 * 2;
                float b0 = __ldg(&bfc[c]), b1 = __ldg(&bfc[c + 1]);
#pragma unroll
                for (int mt = 0; mt < 2; mt++) {
                    d[mt][nt][0] += b0;
                    d[mt][nt][1] += b1;
                    d[mt][nt][2] += b0;
                    d[mt][nt][3] += b1;
                }
            }
            float lm[2][2];
#pragma unroll
            for (int mt = 0; mt < 2; mt++) {
                float m0 = -INFINITY, m1 = -INFINITY;
#pragma unroll
                for (int nt = 0; nt < 8; nt++) {
                    m0 = fmaxf(m0, fmaxf(d[mt][nt][0], d[mt][nt][1]));
                    m1 = fmaxf(m1, fmaxf(d[mt][nt][2], d[mt][nt][3]));
                }
                lm[mt][0] = m0;
                lm[mt][1] = m1;
            }
#pragma unroll
            for (int mt = 0; mt < 2; mt++)
#pragma unroll
                for (int hh = 0; hh < 2; hh++) {
                    float v = lm[mt][hh];
                    v = fmaxf(v, __shfl_xor_sync(0xffffffffu, v, 1));
                    v = fmaxf(v, __shfl_xor_sync(0xffffffffu, v, 2));
                    lm[mt][hh] = v;
                }
            if (t4 == 0) {
#pragma unroll
                for (int mt = 0; mt < 2; mt++)
#pragma unroll
                    for (int hh = 0; hh < 2; hh++)
                        red[wn * 128 + wm * 32 + mt * 16 + hh * 8 + g] = lm[mt][hh];
            }
            __syncthreads();
            if (tid < 128)
                scm[tid] = fmaxf(fmaxf(red[tid], red[128 + tid]),
                                 fmaxf(red[256 + tid], red[384 + tid]));
            __syncthreads();

            float ls[2][2];
#pragma unroll
            for (int mt = 0; mt < 2; mt++)
#pragma unroll
                for (int hh = 0; hh < 2; hh++) {
                    float cm = scm[wm * 32 + mt * 16 + hh * 8 + g];
                    float s = 0.f;
#pragma unroll
                    for (int nt = 0; nt < 8; nt++)
                        s += ex2sum2((d[mt][nt][2 * hh] - cm) * L2E,
                                     (d[mt][nt][2 * hh + 1] - cm) * L2E);
                    ls[mt][hh] = s;
                }
#pragma unroll
            for (int mt = 0; mt < 2; mt++)
#pragma unroll
                for (int hh = 0; hh < 2; hh++) {
                    float v = ls[mt][hh];
                    v += __shfl_xor_sync(0xffffffffu, v, 1);
                    v += __shfl_xor_sync(0xffffffffu, v, 2);
                    ls[mt][hh] = v;
                }
            if (t4 == 0) {
#pragma unroll
                for (int mt = 0; mt < 2; mt++)
#pragma unroll
                    for (int hh = 0; hh < 2; hh++)
                        red[wn * 128 + wm * 32 + mt * 16 + hh * 8 + g] = ls[mt][hh];
            }
            __syncthreads();
            if (tid < 128) {
                float cs = red[tid] + red[128 + tid] + red[256 + tid] + red[384 + tid];
                float mo = rmax[tid];
                float mn = fmaxf(mo, scm[tid]);
                rsum[tid] = rsum[tid] * exp2f((mo - mn) * L2E) +
                            cs * exp2f((scm[tid] - mn) * L2E);
                rmax[tid] = mn;
            }

            if (ch < 3) {
#pragma unroll
                for (int mt = 0; mt < 2; mt++)
#pragma unroll
                    for (int hh = 0; hh < 2; hh++) {
                        size_t r = row0 + wm * 32 + mt * 16 + hh * 8 + g;
#pragma unroll
                        for (int nt = 0; nt < 8; nt++) {
                            int c = ch * 256 + wn * 64 + nt * 8 + t4 * 2;
                            __half2 hv = __floats2half2_rn(d[mt][nt][2 * hh],
                                                           d[mt][nt][2 * hh + 1]);
                            __stcs((__half2*)&g_logits[r * VV + c], hv);
                        }
                    }
#pragma unroll
                for (int mt = 0; mt < 2; mt++)
#pragma unroll
                    for (int nt = 0; nt < 8; nt++)
#pragma unroll
                        for (int q = 0; q < 4; q++) d[mt][nt][q] = 0.f;
            }
        }
    }

    // ---- finalize: rls ----
    __syncthreads();
    if (tid < 128) scm[tid] = logf(rsum[tid]) + rmax[tid];
    __syncthreads();

    // ---- chunk 3 output directly from registers ----
#pragma unroll
    for (int mt = 0; mt < 2; mt++)
#pragma unroll
        for (int hh = 0; hh < 2; hh++) {
            int rl = wm * 32 + mt * 16 + hh * 8 + g;
            float rls = scm[rl];
            size_t r = row0 + rl;
#pragma unroll
            for (int nt = 0; nt < 8; nt++) {
                int c = 768 + wn * 64 + nt * 8 + t4 * 2;
                float2 o;
                o.x = d[mt][nt][2 * hh] - rls;
                o.y = d[mt][nt][2 * hh + 1] - rls;
                __stcs((float2*)&out[r * VV + c], o);
            }
        }

    // ---- normalize staged chunks 0-2 (cols 0..767) ----
    for (int p = tid; p < 128 * 192; p += NTHR) {
        int r = p / 192;
        int c4 = p - r * 192;
        float rls = scm[r];
        uint2 lv = __ldcs((const uint2*)&g_logits[(row0 + r) * VV + c4 * 4]);
        float2 f0 = __half22float2(*(__half2*)&lv.x);
        float2 f1 = __half22float2(*(__half2*)&lv.y);
        float4 o;
        o.x = f0.x - rls;
        o.y = f0.y - rls;
        o.z = f1.x - rls;
        o.w = f1.y - rls;
        __stcs((float4*)&out[(row0 + r) * VV + c4 * 4], o);
    }
}

// ===========================================================================
extern "C" void kernel_launch(void* const* d_in, const int* in_sizes, int n_in,
                              void* d_out, int out_size) {
    const float* enc_out = (const float*)d_in[0];
    const float* pred_out = (const float*)d_in[1];
    const float* W_enc = (const float*)d_in[2];
    const float* b_enc = (const float*)d_in[3];
    const float* W_pred = (const float*)d_in[4];
    const float* b_pred = (const float*)d_in[5];
    const float* W_fc = (const float*)d_in[6];
    const float* b_fc = (const float*)d_in[7];
    float* out = (float*)d_out;

    cudaFuncSetAttribute(joint_gemm, cudaFuncAttributeMaxDynamicSharedMemorySize,
                         SM_TOTAL);

    pre_kernel<<<1040, 256>>>(enc_out, pred_out, W_enc, b_enc, W_pred, b_pred, W_fc);
    joint_gemm<<<MTOT / 128, NTHR, SM_TOTAL>>>(b_fc, out);
}

// round 17
// speedup vs baseline: 1.2542x; 1.2050x over previous
#include <cuda_runtime.h>
#include <cuda_fp16.h>
#include <math.h>
#include <stdint.h>

#define BB 4
#define TT 256
#define UU 64
#define DD 640
#define HH 640
#define VV 1024
#define MTOT (BB*TT*UU)   // 65536
#define L2E 1.4426950408889634f

#define AROW 648          // f16 units per A row in SMEM (joint)
#define BROW 40           // f16 units per B row in SMEM (32 + 8 pad)
#define BROWB 80
#define BBUF (256*BROWB)  // bytes per B stage = 20480 (BK=32)
#define NSTAGE 80         // 4 chunks x 20 stages (32 k each)
#define NTHR 512          // joint: 16 warps

// ---- static device scratch ----
__device__ float  g_enc[BB*TT*HH];
__device__ float  g_pred[BB*UU*HH];
__device__ __half g_w16t[VV*HH];                 // W_fc^T f16: [n][k]
__device__ __half g_logits[(size_t)MTOT*VV];     // staged logits f16 (chunks 0-2)

__device__ __forceinline__ uint32_t smem_u32(const void* p) {
    uint32_t a;
    asm("{ .reg .u64 t; cvta.to.shared.u64 t, %1; cvt.u32.u64 %0, t; }"
        : "=r"(a) : "l"(p));
    return a;
}
__device__ __forceinline__ void cpasync16cg(uint32_t dst, const void* src) {
    asm volatile("cp.async.cg.shared.global [%0], [%1], 16;" ::"r"(dst), "l"(src));
}
#define CP_COMMIT() asm volatile("cp.async.commit_group;")
#define CP_WAIT(n) asm volatile("cp.async.wait_group %0;" ::"n"(n))

__device__ __forceinline__ void ldsm_x4(uint32_t* r, uint32_t addr) {
    asm volatile("ldmatrix.sync.aligned.m8n8.x4.shared.b16 {%0,%1,%2,%3}, [%4];"
                 : "=r"(r[0]), "=r"(r[1]), "=r"(r[2]), "=r"(r[3]) : "r"(addr));
}
__device__ __forceinline__ float ex2sum2(float x0, float x1) {
    __half2 h = __floats2half2_rn(x0, x1);
    unsigned int u = *(unsigned int*)&h, o;
    asm("ex2.approx.f16x2 %0, %1;" : "=r"(o) : "r"(u));
    float2 f = __half22float2(*(__half2*)&o);
    return f.x + f.y;
}
__device__ __forceinline__ uint32_t tanh2(float x0, float x1) {
    __half2 h = __floats2half2_rn(x0, x1);
    unsigned int u = *(unsigned int*)&h, o;
    asm("tanh.approx.f16x2 %0, %1;" : "=r"(o) : "r"(u));
    return o;
}
#define MMA16816(D, A, B0, B1)                                                  \
    asm volatile(                                                               \
        "mma.sync.aligned.m16n8k16.row.col.f32.f16.f16.f32 "                    \
        "{%0,%1,%2,%3}, {%4,%5,%6,%7}, {%8,%9}, {%0,%1,%2,%3};"                 \
        : "+f"((D)[0]), "+f"((D)[1]), "+f"((D)[2]), "+f"((D)[3])                \
        : "r"((A)[0]), "r"((A)[1]), "r"((A)[2]), "r"((A)[3]), "r"(B0), "r"(B1))

// ===========================================================================
// Pre-kernel (ONE launch, 128 threads/block):
//   blocks [0,200)   : tensor-core projections. 1280 rows (1024 enc + 256
//                      pred) x 640 cols, tile 64x64, K=640, BK=32, fp32
//                      inputs converted to f16 during SMEM staging, fp32
//                      accum, bias fused. B staged transposed [n][k].
//   blocks [200,840) : W_fc fp32 [k][n] -> f16 transposed [n][k].
// ===========================================================================
__global__ __launch_bounds__(128) void pre_kernel(const float* __restrict__ enc_out,
                                                  const float* __restrict__ pred_out,
                                                  const float* __restrict__ W_enc,
                                                  const float* __restrict__ b_enc,
                                                  const float* __restrict__ W_pred,
                                                  const float* __restrict__ b_pred,
                                                  const float* __restrict__ Wfc) {
    const int tid = threadIdx.x;
    const int bid = blockIdx.x;

    if (bid >= 200) {
        // ---- W_fc convert: 32x32 tile, 128 threads ----
        __shared__ float t[32][33];
        int i = bid - 200;                 // 0..639
        int n0 = (i & 31) * 32;
        int k0 = (i >> 5) * 32;
        int tx = tid & 31, ty = tid >> 5;  // ty 0..3
#pragma unroll
        for (int j = 0; j < 8; j++)
            t[ty + 4 * j][tx] = Wfc[(size_t)(k0 + ty + 4 * j) * VV + n0 + tx];
        __syncthreads();
#pragma unroll
        for (int j = 0; j < 8; j++)
            g_w16t[(size_t)(n0 + ty + 4 * j) * HH + k0 + tx] =
                __float2half(t[tx][ty + 4 * j]);
        return;
    }

    // ---- tensor-core projection segment ----
    __shared__ __half As[64 * 40];   // [row][k] 32k + 8 pad
    __shared__ __half Bs[64 * 40];   // [n][k]   32k + 8 pad (transposed stage)

    const int mti = bid / 10;        // 0..19
    const int bn = (bid % 10) * 64;
    const float* X;
    const float* W;
    const float* bias;
    float* C;
    int bm;
    if (mti < 16) {
        X = enc_out; W = W_enc; bias = b_enc; C = g_enc; bm = mti * 64;
    } else {
        X = pred_out; W = W_pred; bias = b_pred; C = g_pred; bm = (mti - 16) * 64;
    }

    const int lane = tid & 31;
    const int warp = tid >> 5;
    const int wm = warp >> 1;   // 0..1 -> rows 32*wm
    const int wn = warp & 1;    // 0..1 -> cols 32*wn
    const int g = lane >> 2;
    const int t4 = lane & 3;

    float d[2][4][4];
#pragma unroll
    for (int mt = 0; mt < 2; mt++)
#pragma unroll
        for (int nt = 0; nt < 4; nt++)
#pragma unroll
            for (int q = 0; q < 4; q++) d[mt][nt][q] = 0.f;

    const uint32_t sA = smem_u32(As);
    const uint32_t sB = smem_u32(Bs);
    const uint32_t a_frag =
        sA + ((uint32_t)(wm * 32 + (lane & 15)) * 40 + ((lane >> 4) << 3)) * 2;
    const uint32_t b_frag =
        sB + ((uint32_t)(wn * 32 + (lane & 7) + ((lane >> 4) << 3)) * 40 +
              (((lane >> 3) & 1) << 3)) * 2;

    // staging roles
    const int ar = tid >> 1, akh = tid & 1;       // A: row, k-half (16 k)
    const int bkk = tid >> 2, bj = tid & 3;       // B: k row, 16-n group

    for (int k0 = 0; k0 < DD; k0 += 32) {
        __syncthreads();   // previous compute done (buffers reusable)
        // ---- A stage: X[bm+ar][k0 + akh*16 .. +16] -> f16 ----
        {
            const float* src = X + (size_t)(bm + ar) * DD + k0 + akh * 16;
            float4 f0 = *(const float4*)(src);
            float4 f1 = *(const float4*)(src + 4);
            float4 f2 = *(const float4*)(src + 8);
            float4 f3 = *(const float4*)(src + 12);
            __half2 h0 = __floats2half2_rn(f0.x, f0.y);
            __half2 h1 = __floats2half2_rn(f0.z, f0.w);
            __half2 h2 = __floats2half2_rn(f1.x, f1.y);
            __half2 h3 = __floats2half2_rn(f1.z, f1.w);
            __half2 h4 = __floats2half2_rn(f2.x, f2.y);
            __half2 h5 = __floats2half2_rn(f2.z, f2.w);
            __half2 h6 = __floats2half2_rn(f3.x, f3.y);
            __half2 h7 = __floats2half2_rn(f3.z, f3.w);
            uint4 o0, o1;
            o0.x = *(uint32_t*)&h0; o0.y = *(uint32_t*)&h1;
            o0.z = *(uint32_t*)&h2; o0.w = *(uint32_t*)&h3;
            o1.x = *(uint32_t*)&h4; o1.y = *(uint32_t*)&h5;
            o1.z = *(uint32_t*)&h6; o1.w = *(uint32_t*)&h7;
            uint4* dst = (uint4*)&As[ar * 40 + akh * 16];
            dst[0] = o0;
            dst[1] = o1;
        }
        // ---- B stage: W[k0+bkk][bn + bj*16 .. +16] -> transposed [n][k] ----
        {
            const float* src = W + (size_t)(k0 + bkk) * HH + bn + bj * 16;
            float4 f0 = *(const float4*)(src);
            float4 f1 = *(const float4*)(src + 4);
            float4 f2 = *(const float4*)(src + 8);
            float4 f3 = *(const float4*)(src + 12);
            float v[16] = {f0.x, f0.y, f0.z, f0.w, f1.x, f1.y, f1.z, f1.w,
                           f2.x, f2.y, f2.z, f2.w, f3.x, f3.y, f3.z, f3.w};
#pragma unroll
            for (int i = 0; i < 16; i++)
                Bs[(bj * 16 + i) * 40 + bkk] = __float2half(v[i]);
        }
        __syncthreads();   // stage visible

        // ---- compute: 2 x 16-k sub-steps ----
#pragma unroll
        for (int s = 0; s < 2; s++) {
            uint32_t a[2][4];
#pragma unroll
            for (int mt = 0; mt < 2; mt++)
                ldsm_x4(a[mt], a_frag + s * 32 + mt * 16 * 80);
#pragma unroll
            for (int p = 0; p < 2; p++) {
                uint32_t b[4];
                ldsm_x4(b, b_frag + s * 32 + p * 16 * 80);
#pragma unroll
                for (int mt = 0; mt < 2; mt++) {
                    MMA16816(d[mt][2 * p], a[mt], b[0], b[1]);
                    MMA16816(d[mt][2 * p + 1], a[mt], b[2], b[3]);
                }
            }
        }
    }

    // ---- epilogue: bias + fp32 store ----
#pragma unroll
    for (int mt = 0; mt < 2; mt++)
#pragma unroll
        for (int hh = 0; hh < 2; hh++) {
            int row = bm + wm * 32 + mt * 16 + hh * 8 + g;
#pragma unroll
            for (int nt = 0; nt < 4; nt++) {
                int col = bn + wn * 32 + nt * 8 + t4 * 2;
                float2 o;
                o.x = d[mt][nt][2 * hh] + __ldg(&bias[col]);
                o.y = d[mt][nt][2 * hh + 1] + __ldg(&bias[col + 1]);
                *(float2*)&C[(size_t)row * HH + col] = o;
            }
        }
}

// ===========================================================================
// Main kernel (R13, at the fallback-HMMA throughput wall): M-tile 128,
// 512 threads, warp tile 32x64, BK=32 stages / 3 buffers, fused tanh
// prologue, online log-softmax, chunks 0-2 staged f16, chunk 3 direct.
// ===========================================================================
#define SM_A 0
#define SM_B (128 * AROW * 2)          // 165888
#define SM_RED (SM_B + 3 * BBUF)       // 227328
#define SM_SCM (SM_RED + 2048)         // 229376
#define SM_RMAX (SM_SCM + 512)         // 229888
#define SM_RSUM (SM_RMAX + 512)        // 230400
#define SM_TOTAL (SM_RSUM + 512)       // 230912

__global__ __launch_bounds__(NTHR, 1) void joint_gemm(const float* __restrict__ bfc,
                                                      float* __restrict__ out) {
    extern __shared__ char smc[];
    const uint32_t sbase = smem_u32(smc);
    float* red = (float*)(smc + SM_RED);
    float* scm = (float*)(smc + SM_SCM);
    float* rmax = (float*)(smc + SM_RMAX);
    float* rsum = (float*)(smc + SM_RSUM);

    const int tid = threadIdx.x;
    const int lane = tid & 31;
    const int warp = tid >> 5;
    const int wm = warp >> 2;
    const int wn = warp & 3;
    const int g = lane >> 2;
    const int t4 = lane & 3;
    const size_t row0 = (size_t)blockIdx.x * 128;

    const int bn_row = tid >> 1;
    const int bh = tid & 1;
    const uint32_t bdst0 = sbase + SM_B + bn_row * BROWB + bh * 32;
    const __half* bsrc = g_w16t + (size_t)bn_row * HH + bh * 16;

    cpasync16cg(bdst0 + 0 * BBUF, bsrc);
    cpasync16cg(bdst0 + 0 * BBUF + 16, bsrc + 8);
    CP_COMMIT();
    cpasync16cg(bdst0 + 1 * BBUF, bsrc + 32);
    cpasync16cg(bdst0 + 1 * BBUF + 16, bsrc + 40);
    CP_COMMIT();
    bsrc += 64;
    int lks = 2;
    int pbuf = 2;

    {
        const float* predb = g_pred + (row0 / (TT * UU)) * (size_t)(UU * HH);
        for (int e = tid; e < 128 * 160; e += NTHR) {
            int i = e / 160;
            int h4 = (e - i * 160) * 4;
            const float* encr = g_enc + (size_t)((row0 + i) >> 6) * HH;
            const float* predr = predb + (size_t)((row0 + i) & 63) * HH;
            float4 p = *(const float4*)&predr[h4];
            float4 q = *(const float4*)&encr[h4];
            uint2 o;
            o.x = tanh2(p.x + q.x, p.y + q.y);
            o.y = tanh2(p.z + q.z, p.w + q.w);
            *(uint2*)(smc + SM_A + i * (AROW * 2) + h4 * 2) = o;
        }
    }
    if (tid < 128) {
        rmax[tid] = -INFINITY;
        rsum[tid] = 0.f;
    }

    float d[2][8][4];
#pragma unroll
    for (int mt = 0; mt < 2; mt++)
#pragma unroll
        for (int nt = 0; nt < 8; nt++)
#pragma unroll
            for (int q = 0; q < 4; q++) d[mt][nt][q] = 0.f;

    const uint32_t a_lane_row = (uint32_t)(wm * 32 + (lane & 15));
    const uint32_t a_lane_coloff = (uint32_t)((lane >> 4) << 3);
    const uint32_t b_lane_n = (uint32_t)(wn * 64 + (lane & 7) + ((lane >> 4) << 3));
    const uint32_t b_lane_koff = (uint32_t)(((lane >> 3) & 1) << 3);

    const uint32_t abase0 =
        sbase + SM_A + (a_lane_row * AROW + a_lane_coloff) * 2;
    const uint32_t bfrag0 = sbase + SM_B + (b_lane_n * BROW + b_lane_koff) * 2;

    int gs = 0;
    int cbuf = 0;
    for (int ch = 0; ch < 4; ch++) {
        uint32_t abase = abase0;
        for (int it = 0; it < 20; it++, gs++) {
            __syncthreads();

            if (gs + 2 < NSTAGE) {
                cpasync16cg(bdst0 + pbuf * BBUF, bsrc);
                cpasync16cg(bdst0 + pbuf * BBUF + 16, bsrc + 8);
                CP_COMMIT();
                CP_WAIT(2);
                if (++lks == 20) {
                    lks = 0;
                    bsrc += 256 * HH - 19 * 32;
                } else {
                    bsrc += 32;
                }
                if (++pbuf == 3) pbuf = 0;
            } else {
                CP_WAIT(0);
            }
            __syncthreads();

            const uint32_t bstage = bfrag0 + (uint32_t)cbuf * BBUF;
            if (++cbuf == 3) cbuf = 0;

#pragma unroll
            for (int s = 0; s < 2; s++) {
                uint32_t a[2][4];
#pragma unroll
                for (int mt = 0; mt < 2; mt++)
                    ldsm_x4(a[mt], abase + s * 32 + mt * 16 * (AROW * 2));
                const uint32_t bb = bstage + s * 32;
#pragma unroll
                for (int p = 0; p < 4; p++) {
                    uint32_t b[4];
                    ldsm_x4(b, bb + p * 16 * (BROW * 2));
#pragma unroll
                    for (int mt = 0; mt < 2; mt++) {
                        MMA16816(d[mt][2 * p], a[mt], b[0], b[1]);
                        MMA16816(d[mt][2 * p + 1], a[mt], b[2], b[3]);
                    }
                }
            }
            abase += 64;
        }

        // ================= per-chunk epilogue =================
        {
#pragma unroll
            for (int nt = 0; nt < 8; nt++) {
                int c = ch * 256 + wn * 64 + nt * 8 + t4 * 2;
                float b0 = __ldg(&bfc[c]), b1 = __ldg(&bfc[c + 1]);
#pragma unroll
                for (int mt = 0; mt < 2; mt++) {
                    d[mt][nt][0] += b0;
                    d[mt][nt][1] += b1;
                    d[mt][nt][2] += b0;
                    d[mt][nt][3] += b1;
                }
            }
            float lm[2][2];
#pragma unroll
            for (int mt = 0; mt < 2; mt++) {
                float m0 = -INFINITY, m1 = -INFINITY;
#pragma unroll
                for (int nt = 0; nt < 8; nt++) {
                    m0 = fmaxf(m0, fmaxf(d[mt][nt][0], d[mt][nt][1]));
                    m1 = fmaxf(m1, fmaxf(d[mt][nt][2], d[mt][nt][3]));
                }
                lm[mt][0] = m0;
                lm[mt][1] = m1;
            }
#pragma unroll
            for (int mt = 0; mt < 2; mt++)
#pragma unroll
                for (int hh = 0; hh < 2; hh++) {
                    float v = lm[mt][hh];
                    v = fmaxf(v, __shfl_xor_sync(0xffffffffu, v, 1));
                    v = fmaxf(v, __shfl_xor_sync(0xffffffffu, v, 2));
                    lm[mt][hh] = v;
                }
            if (t4 == 0) {
#pragma unroll
                for (int mt = 0; mt < 2; mt++)
#pragma unroll
                    for (int hh = 0; hh < 2; hh++)
                        red[wn * 128 + wm * 32 + mt * 16 + hh * 8 + g] = lm[mt][hh];
            }
            __syncthreads();
            if (tid < 128)
                scm[tid] = fmaxf(fmaxf(red[tid], red[128 + tid]),
                                 fmaxf(red[256 + tid], red[384 + tid]));
            __syncthreads();

            float ls[2][2];
#pragma unroll
            for (int mt = 0; mt < 2; mt++)
#pragma unroll
                for (int hh = 0; hh < 2; hh++) {
                    float cm = scm[wm * 32 + mt * 16 + hh * 8 + g];
                    float s = 0.f;
#pragma unroll
                    for (int nt = 0; nt < 8; nt++)
                        s += ex2sum2((d[mt][nt][2 * hh] - cm) * L2E,
                                     (d[mt][nt][2 * hh + 1] - cm) * L2E);
                    ls[mt][hh] = s;
                }
#pragma unroll
            for (int mt = 0; mt < 2; mt++)
#pragma unroll
                for (int hh = 0; hh < 2; hh++) {
                    float v = ls[mt][hh];
                    v += __shfl_xor_sync(0xffffffffu, v, 1);
                    v += __shfl_xor_sync(0xffffffffu, v, 2);
                    ls[mt][hh] = v;
                }
            if (t4 == 0) {
#pragma unroll
                for (int mt = 0; mt < 2; mt++)
#pragma unroll
                    for (int hh = 0; hh < 2; hh++)
                        red[wn * 128 + wm * 32 + mt * 16 + hh * 8 + g] = ls[mt][hh];
            }
            __syncthreads();
            if (tid < 128) {
                float cs = red[tid] + red[128 + tid] + red[256 + tid] + red[384 + tid];
                float mo = rmax[tid];
                float mn = fmaxf(mo, scm[tid]);
                rsum[tid] = rsum[tid] * exp2f((mo - mn) * L2E) +
                            cs * exp2f((scm[tid] - mn) * L2E);
                rmax[tid] = mn;
            }

            if (ch < 3) {
#pragma unroll
                for (int mt = 0; mt < 2; mt++)
#pragma unroll
                    for (int hh = 0; hh < 2; hh++) {
                        size_t r = row0 + wm * 32 + mt * 16 + hh * 8 + g;
#pragma unroll
                        for (int nt = 0; nt < 8; nt++) {
                            int c = ch * 256 + wn * 64 + nt * 8 + t4 * 2;
                            __half2 hv = __floats2half2_rn(d[mt][nt][2 * hh],
                                                           d[mt][nt][2 * hh + 1]);
                            __stcs((__half2*)&g_logits[r * VV + c], hv);
                        }
                    }
#pragma unroll
                for (int mt = 0; mt < 2; mt++)
#pragma unroll
                    for (int nt = 0; nt < 8; nt++)
#pragma unroll
                        for (int q = 0; q < 4; q++) d[mt][nt][q] = 0.f;
            }
        }
    }

    __syncthreads();
    if (tid < 128) scm[tid] = logf(rsum[tid]) + rmax[tid];
    __syncthreads();

#pragma unroll
    for (int mt = 0; mt < 2; mt++)
#pragma unroll
        for (int hh = 0; hh < 2; hh++) {
            int rl = wm * 32 + mt * 16 + hh * 8 + g;
            float rls = scm[rl];
            size_t r = row0 + rl;
#pragma unroll
            for (int nt = 0; nt < 8; nt++) {
                int c = 768 + wn * 64 + nt * 8 + t4 * 2;
                float2 o;
                o.x = d[mt][nt][2 * hh] - rls;
                o.y = d[mt][nt][2 * hh + 1] - rls;
                __stcs((float2*)&out[r * VV + c], o);
            }
        }

    for (int p = tid; p < 128 * 192; p += NTHR) {
        int r = p / 192;
        int c4 = p - r * 192;
        float rls = scm[r];
        uint2 lv = __ldcs((const uint2*)&g_logits[(row0 + r) * VV + c4 * 4]);
        float2 f0 = __half22float2(*(__half2*)&lv.x);
        float2 f1 = __half22float2(*(__half2*)&lv.y);
        float4 o;
        o.x = f0.x - rls;
        o.y = f0.y - rls;
        o.z = f1.x - rls;
        o.w = f1.y - rls;
        __stcs((float4*)&out[(row0 + r) * VV + c4 * 4], o);
    }
}

// ===========================================================================
extern "C" void kernel_launch(void* const* d_in, const int* in_sizes, int n_in,
                              void* d_out, int out_size) {
    const float* enc_out = (const float*)d_in[0];
    const float* pred_out = (const float*)d_in[1];
    const float* W_enc = (const float*)d_in[2];
    const float* b_enc = (const float*)d_in[3];
    const float* W_pred = (const float*)d_in[4];
    const float* b_pred = (const float*)d_in[5];
    const float* W_fc = (const float*)d_in[6];
    const float* b_fc = (const float*)d_in[7];
    float* out = (float*)d_out;

    cudaFuncSetAttribute(joint_gemm, cudaFuncAttributeMaxDynamicSharedMemorySize,
                         SM_TOTAL);

    pre_kernel<<<840, 128>>>(enc_out, pred_out, W_enc, b_enc, W_pred, b_pred, W_fc);
    joint_gemm<<<MTOT / 128, NTHR, SM_TOTAL>>>(b_fc, out);
}